// round 1
// baseline (speedup 1.0000x reference)
#include <cuda_runtime.h>
#include <math.h>

// Problem constants
#define S_LEN 2048
#define BATCH 2
#define EMB   2048
#define HEADS 32
#define HDIM  64
#define MROWS (S_LEN * BATCH)          // 4096 flattened (s,b) rows
#define QKV_N (3 * EMB)                // 6144
#define MASK_NEG (-66504.0f)

// ---------------------------------------------------------------------------
// Scratch (static device globals — no runtime allocation allowed)
// ---------------------------------------------------------------------------
__device__ float g_qkv[(size_t)MROWS * QKV_N];                 // [4096, 6144]
__device__ float g_q  [(size_t)BATCH * HEADS * S_LEN * HDIM];  // [b][h][s][d]
__device__ float g_k  [(size_t)BATCH * HEADS * S_LEN * HDIM];
__device__ float g_v  [(size_t)BATCH * HEADS * S_LEN * HDIM];
__device__ float g_ctx[(size_t)MROWS * EMB];                   // [4096, 2048]

// ---------------------------------------------------------------------------
// SGEMM: C[M,N] = A[M,K] @ B[K,N] + bias[N]
// 128x128 tile, BK=8, 8x8 per thread, 256 threads.
// ---------------------------------------------------------------------------
template <int BM, int BN, int BK, int TM, int TN>
__global__ __launch_bounds__(256)
void sgemm_bias(int M, int N, int K,
                const float* __restrict__ A,
                const float* __restrict__ B,
                const float* __restrict__ bias,
                float* __restrict__ C) {
    __shared__ float As[BK][BM];
    __shared__ float Bs[BK][BN];

    const int tid  = threadIdx.x;
    const int bRow = blockIdx.y * BM;
    const int bCol = blockIdx.x * BN;

    const int tCol = tid % (BN / TN);   // 0..15
    const int tRow = tid / (BN / TN);   // 0..15

    // A-tile loader: each thread one float4 along K
    const int aRow = tid / (BK / 4);        // 0..127
    const int aCol = (tid % (BK / 4)) * 4;  // 0 or 4
    // B-tile loader: each thread one float4 along N
    const int bRowL = tid / (BN / 4);       // 0..7
    const int bColL = (tid % (BN / 4)) * 4; // 0..124

    float acc[TM][TN];
#pragma unroll
    for (int i = 0; i < TM; ++i)
#pragma unroll
        for (int j = 0; j < TN; ++j) acc[i][j] = 0.0f;

    float regM[TM], regN[TN];

    const float* Aptr = A + (size_t)bRow * K;
    const float* Bptr = B + bCol;

    for (int k0 = 0; k0 < K; k0 += BK) {
        float4 a4 = *reinterpret_cast<const float4*>(Aptr + (size_t)aRow * K + k0 + aCol);
        As[aCol + 0][aRow] = a4.x;
        As[aCol + 1][aRow] = a4.y;
        As[aCol + 2][aRow] = a4.z;
        As[aCol + 3][aRow] = a4.w;
        *reinterpret_cast<float4*>(&Bs[bRowL][bColL]) =
            *reinterpret_cast<const float4*>(Bptr + (size_t)(k0 + bRowL) * N + bColL);
        __syncthreads();

#pragma unroll
        for (int k = 0; k < BK; ++k) {
#pragma unroll
            for (int i = 0; i < TM; ++i) regM[i] = As[k][tRow * TM + i];
#pragma unroll
            for (int j = 0; j < TN; ++j) regN[j] = Bs[k][tCol * TN + j];
#pragma unroll
            for (int i = 0; i < TM; ++i)
#pragma unroll
                for (int j = 0; j < TN; ++j)
                    acc[i][j] += regM[i] * regN[j];
        }
        __syncthreads();
    }

#pragma unroll
    for (int i = 0; i < TM; ++i) {
#pragma unroll
        for (int j = 0; j < TN; j += 4) {
            int col = bCol + tCol * TN + j;
            float4 o;
            o.x = acc[i][j + 0] + bias[col + 0];
            o.y = acc[i][j + 1] + bias[col + 1];
            o.z = acc[i][j + 2] + bias[col + 2];
            o.w = acc[i][j + 3] + bias[col + 3];
            *reinterpret_cast<float4*>(C + (size_t)(bRow + tRow * TM + i) * N + col) = o;
        }
    }
}

// ---------------------------------------------------------------------------
// RoPE + split: qkv[4096,6144] -> Q/K/V [b][h][s][d] with rotary on Q,K
// GPT-NeoX style: rotate_half over full head dim (pairs d <-> d+32).
// ---------------------------------------------------------------------------
__global__ __launch_bounds__(256)
void rope_split_kernel() {
    int idx = blockIdx.x * blockDim.x + threadIdx.x;   // over S*B*H*D = 8388608
    int d = idx & 63;
    int h = (idx >> 6) & 31;
    int b = (idx >> 11) & 1;
    int s = idx >> 12;

    const float* base = g_qkv + (size_t)(s * BATCH + b) * QKV_N;
    int col = h * HDIM + d;

    float qv = base[col];
    float kv = base[EMB + col];
    float vv = base[2 * EMB + col];

    int i = d & 31;  // freq index (emb = concat([freqs, freqs]))
    float inv_freq = powf(10000.0f, -(float)i / 32.0f);
    float ang = (float)s * inv_freq;
    float sn, cs;
    sincosf(ang, &sn, &cs);

    float qpair, kpair;
    if (d < 32) {
        qpair = -base[col + 32];
        kpair = -base[EMB + col + 32];
    } else {
        qpair = base[col - 32];
        kpair = base[EMB + col - 32];
    }

    size_t o = ((size_t)(b * HEADS + h) * S_LEN + s) * HDIM + d;
    g_q[o] = qv * cs + qpair * sn;
    g_k[o] = kv * cs + kpair * sn;
    g_v[o] = vv;
}

// ---------------------------------------------------------------------------
// Causal flash-style attention.
// Grid: (S/64, B*H). Block: 256 threads.
// Thread t owns row r = t>>2 of the 64-query tile and a 16-wide slice
// (sl = t&3) of either the key tile (score phase) or head dim (PV phase).
// Static smem exactly 48KB: Q[64][64] + KV[64][64] (K^T then V) + P[64][64].
// ---------------------------------------------------------------------------
__global__ __launch_bounds__(256)
void attn_kernel() {
    __shared__ float Qs[64][64];
    __shared__ float KVs[64][64];
    __shared__ float Ps[64][64];

    const int bh = blockIdx.y;          // b*HEADS + h
    const int q0 = blockIdx.x * 64;
    const int t  = threadIdx.x;
    const int r  = t >> 2;
    const int sl = t & 3;
    const int c0 = sl * 16;

    const float* Qh = g_q + (size_t)bh * S_LEN * HDIM;
    const float* Kh = g_k + (size_t)bh * S_LEN * HDIM;
    const float* Vh = g_v + (size_t)bh * S_LEN * HDIM;

    // Load Q tile (64x64 floats = 1024 float4)
    {
        const float4* src = reinterpret_cast<const float4*>(Qh + (size_t)q0 * HDIM);
        float4* dst = reinterpret_cast<float4*>(&Qs[0][0]);
        for (int i = t; i < 1024; i += 256) dst[i] = src[i];
    }

    const float scale = 0.125f;  // 1/sqrt(64)
    float m = -1e30f, l = 0.0f;
    float acc[16];
#pragma unroll
    for (int j = 0; j < 16; ++j) acc[j] = 0.0f;

    const int nkt = blockIdx.x + 1;  // causal: key tiles 0..qtile
    for (int kt = 0; kt < nkt; ++kt) {
        const int k0 = kt * 64;
        __syncthreads();  // previous PV reads of KVs/Ps done (and Q load on iter 0)

        // Load K tile transposed: KVs[d][c] = K[k0+c][d]
        for (int i = t; i < 1024; i += 256) {
            int c = i >> 4;
            int d4 = (i & 15) << 2;
            float4 k4 = *reinterpret_cast<const float4*>(Kh + (size_t)(k0 + c) * HDIM + d4);
            KVs[d4 + 0][c] = k4.x;
            KVs[d4 + 1][c] = k4.y;
            KVs[d4 + 2][c] = k4.z;
            KVs[d4 + 3][c] = k4.w;
        }
        __syncthreads();

        // Scores: s[j] = Q[r,:] . K[c0+j,:]
        float s[16];
#pragma unroll
        for (int j = 0; j < 16; ++j) s[j] = 0.0f;
        for (int d = 0; d < 64; ++d) {
            float qv = Qs[r][d];
#pragma unroll
            for (int j = 0; j < 16; ++j) s[j] += qv * KVs[d][c0 + j];
        }
#pragma unroll
        for (int j = 0; j < 16; ++j) s[j] *= scale;

        if (kt == nkt - 1) {  // diagonal tile: apply causal mask
#pragma unroll
            for (int j = 0; j < 16; ++j)
                if (k0 + c0 + j > q0 + r) s[j] += MASK_NEG;
        }

        // Online softmax (row spread over 4 consecutive lanes)
        float mt = s[0];
#pragma unroll
        for (int j = 1; j < 16; ++j) mt = fmaxf(mt, s[j]);
        mt = fmaxf(mt, __shfl_xor_sync(0xffffffffu, mt, 1));
        mt = fmaxf(mt, __shfl_xor_sync(0xffffffffu, mt, 2));

        float mnew = fmaxf(m, mt);
        float corr = __expf(m - mnew);
        float psum = 0.0f;
#pragma unroll
        for (int j = 0; j < 16; ++j) {
            float p = __expf(s[j] - mnew);
            Ps[r][c0 + j] = p;
            psum += p;
        }
        psum += __shfl_xor_sync(0xffffffffu, psum, 1);
        psum += __shfl_xor_sync(0xffffffffu, psum, 2);
        l = l * corr + psum;
        m = mnew;
#pragma unroll
        for (int j = 0; j < 16; ++j) acc[j] *= corr;

        __syncthreads();  // everyone done reading K and writing P

        // Load V tile: KVs[c][d] = V[k0+c][d]
        for (int i = t; i < 1024; i += 256) {
            int c = i >> 4;
            int d4 = (i & 15) << 2;
            *reinterpret_cast<float4*>(&KVs[c][d4]) =
                *reinterpret_cast<const float4*>(Vh + (size_t)(k0 + c) * HDIM + d4);
        }
        __syncthreads();

        // PV: acc[j] += P[r][c] * V[c][d0+j], d0 = c0
        for (int c = 0; c < 64; ++c) {
            float p = Ps[r][c];
#pragma unroll
            for (int j = 0; j < 16; ++j) acc[j] += p * KVs[c][c0 + j];
        }
    }

    // Normalize and write ctx[(q0+r)*B + b][h*64 + d0+j]
    float inv_l = 1.0f / l;
    int b = bh >> 5;
    int h = bh & 31;
    float* dst = g_ctx + (size_t)((q0 + r) * BATCH + b) * EMB + h * HDIM + c0;
#pragma unroll
    for (int j4 = 0; j4 < 16; j4 += 4) {
        float4 o;
        o.x = acc[j4 + 0] * inv_l;
        o.y = acc[j4 + 1] * inv_l;
        o.z = acc[j4 + 2] * inv_l;
        o.w = acc[j4 + 3] * inv_l;
        *reinterpret_cast<float4*>(dst + j4) = o;
    }
}

// ---------------------------------------------------------------------------
// Launch
// ---------------------------------------------------------------------------
extern "C" void kernel_launch(void* const* d_in, const int* in_sizes, int n_in,
                              void* d_out, int out_size) {
    const float* hs    = (const float*)d_in[0];  // [S,B,E] -> [4096, 2048]
    const float* qkv_w = (const float*)d_in[1];  // [2048, 6144]
    const float* qkv_b = (const float*)d_in[2];  // [6144]
    const float* out_w = (const float*)d_in[3];  // [2048, 2048]
    const float* out_b = (const float*)d_in[4];  // [2048]
    float* out = (float*)d_out;                  // [4096, 2048]

    float *qkv, *ctx;
    cudaGetSymbolAddress((void**)&qkv, g_qkv);
    cudaGetSymbolAddress((void**)&ctx, g_ctx);

    // 1. QKV projection: [4096,2048] @ [2048,6144] + bias
    {
        dim3 grid(QKV_N / 128, MROWS / 128);
        sgemm_bias<128, 128, 8, 8, 8><<<grid, 256>>>(MROWS, QKV_N, EMB,
                                                     hs, qkv_w, qkv_b, qkv);
    }

    // 2. RoPE + split into Q/K/V [b][h][s][d]
    rope_split_kernel<<<(S_LEN * BATCH * HEADS * HDIM) / 256, 256>>>();

    // 3. Causal attention -> ctx [4096, 2048]
    {
        dim3 grid(S_LEN / 64, BATCH * HEADS);
        attn_kernel<<<grid, 256>>>();
    }

    // 4. Output projection: [4096,2048] @ [2048,2048] + bias
    {
        dim3 grid(EMB / 128, MROWS / 128);
        sgemm_bias<128, 128, 8, 8, 8><<<grid, 256>>>(MROWS, EMB, EMB,
                                                     ctx, out_w, out_b, out);
    }
}

// round 2
// speedup vs baseline: 1.8540x; 1.8540x over previous
#include <cuda_runtime.h>
#include <math.h>

// Problem constants
#define S_LEN 2048
#define BATCH 2
#define EMB   2048
#define HEADS 32
#define HDIM  64
#define MROWS (S_LEN * BATCH)          // 4096 flattened (s,b) rows
#define QKV_N (3 * EMB)                // 6144
#define MASK_NEG (-66504.0f)

// ---------------------------------------------------------------------------
// Scratch (static device globals — no runtime allocation allowed)
// ---------------------------------------------------------------------------
__device__ float g_qkv[(size_t)MROWS * QKV_N];                 // [4096, 6144]
__device__ float g_q  [(size_t)BATCH * HEADS * S_LEN * HDIM];  // [b][h][s][d]
__device__ float g_k  [(size_t)BATCH * HEADS * S_LEN * HDIM];
__device__ float g_v  [(size_t)BATCH * HEADS * S_LEN * HDIM];
__device__ float g_ctx[(size_t)MROWS * EMB];                   // [4096, 2048]

// ---------------------------------------------------------------------------
// SGEMM: C[M,N] = A[M,K] @ B[K,N] + bias[N]  (unchanged from round 1)
// ---------------------------------------------------------------------------
template <int BM, int BN, int BK, int TM, int TN>
__global__ __launch_bounds__(256)
void sgemm_bias(int M, int N, int K,
                const float* __restrict__ A,
                const float* __restrict__ B,
                const float* __restrict__ bias,
                float* __restrict__ C) {
    __shared__ float As[BK][BM];
    __shared__ float Bs[BK][BN];

    const int tid  = threadIdx.x;
    const int bRow = blockIdx.y * BM;
    const int bCol = blockIdx.x * BN;

    const int tCol = tid % (BN / TN);
    const int tRow = tid / (BN / TN);

    const int aRow = tid / (BK / 4);
    const int aCol = (tid % (BK / 4)) * 4;
    const int bRowL = tid / (BN / 4);
    const int bColL = (tid % (BN / 4)) * 4;

    float acc[TM][TN];
#pragma unroll
    for (int i = 0; i < TM; ++i)
#pragma unroll
        for (int j = 0; j < TN; ++j) acc[i][j] = 0.0f;

    float regM[TM], regN[TN];

    const float* Aptr = A + (size_t)bRow * K;
    const float* Bptr = B + bCol;

    for (int k0 = 0; k0 < K; k0 += BK) {
        float4 a4 = *reinterpret_cast<const float4*>(Aptr + (size_t)aRow * K + k0 + aCol);
        As[aCol + 0][aRow] = a4.x;
        As[aCol + 1][aRow] = a4.y;
        As[aCol + 2][aRow] = a4.z;
        As[aCol + 3][aRow] = a4.w;
        *reinterpret_cast<float4*>(&Bs[bRowL][bColL]) =
            *reinterpret_cast<const float4*>(Bptr + (size_t)(k0 + bRowL) * N + bColL);
        __syncthreads();

#pragma unroll
        for (int k = 0; k < BK; ++k) {
#pragma unroll
            for (int i = 0; i < TM; ++i) regM[i] = As[k][tRow * TM + i];
#pragma unroll
            for (int j = 0; j < TN; ++j) regN[j] = Bs[k][tCol * TN + j];
#pragma unroll
            for (int i = 0; i < TM; ++i)
#pragma unroll
                for (int j = 0; j < TN; ++j)
                    acc[i][j] += regM[i] * regN[j];
        }
        __syncthreads();
    }

#pragma unroll
    for (int i = 0; i < TM; ++i) {
#pragma unroll
        for (int j = 0; j < TN; j += 4) {
            int col = bCol + tCol * TN + j;
            float4 o;
            o.x = acc[i][j + 0] + bias[col + 0];
            o.y = acc[i][j + 1] + bias[col + 1];
            o.z = acc[i][j + 2] + bias[col + 2];
            o.w = acc[i][j + 3] + bias[col + 3];
            *reinterpret_cast<float4*>(C + (size_t)(bRow + tRow * TM + i) * N + col) = o;
        }
    }
}

// ---------------------------------------------------------------------------
// RoPE + split
// ---------------------------------------------------------------------------
__global__ __launch_bounds__(256)
void rope_split_kernel() {
    int idx = blockIdx.x * blockDim.x + threadIdx.x;
    int d = idx & 63;
    int h = (idx >> 6) & 31;
    int b = (idx >> 11) & 1;
    int s = idx >> 12;

    const float* base = g_qkv + (size_t)(s * BATCH + b) * QKV_N;
    int col = h * HDIM + d;

    float qv = base[col];
    float kv = base[EMB + col];
    float vv = base[2 * EMB + col];

    int i = d & 31;
    // inv_freq = 10000^(-i/32) = exp(-i * ln(10000)/32)
    float inv_freq = __expf(-0.28782252f * (float)i);
    float ang = (float)s * inv_freq;
    float sn, cs;
    sincosf(ang, &sn, &cs);

    float qpair, kpair;
    if (d < 32) {
        qpair = -base[col + 32];
        kpair = -base[EMB + col + 32];
    } else {
        qpair = base[col - 32];
        kpair = base[EMB + col - 32];
    }

    size_t o = ((size_t)(b * HEADS + h) * S_LEN + s) * HDIM + d;
    g_q[o] = qv * cs + qpair * sn;
    g_k[o] = kv * cs + kpair * sn;
    g_v[o] = vv;
}

// ---------------------------------------------------------------------------
// Causal flash attention v2 — register-blocked (GEMM-style outer products).
// Grid: (S/64, B*H). Block: 256 threads.
// Thread (ty,tx): ty=t/16 -> q-rows 4ty..4ty+3; tx=t%16 -> key cols (score
// phase) / head dims (PV phase) 4tx..4tx+3. 4x4 register tile, 16 FMA per
// 2x LDS.128.
// Layouts: Qs[d][r], KVs = K as [d][c] then V as [c][d], Ps[c][r] with XOR
// float4-column swizzle (pcol = ty ^ (c&15)) for conflict-free store+read.
// ---------------------------------------------------------------------------
__global__ __launch_bounds__(256)
void attn_kernel() {
    __shared__ float Qs[64][64];   // [d][r]
    __shared__ float KVs[64][64];  // K phase: [d][c]; V phase: [c][d]
    __shared__ float Ps[64][64];   // [c][swizzled r]

    const int bh = blockIdx.y;
    const int q0 = blockIdx.x * 64;
    const int t  = threadIdx.x;
    const int ty = t >> 4;     // 0..15
    const int tx = t & 15;     // 0..15
    const int r0 = ty * 4;
    const int x0 = tx * 4;

    const float* Qh = g_q + (size_t)bh * S_LEN * HDIM;
    const float* Kh = g_k + (size_t)bh * S_LEN * HDIM;
    const float* Vh = g_v + (size_t)bh * S_LEN * HDIM;

    // Load Q transposed: lane -> row (conflict-free transposed store)
    {
        const int rr = t & 63;
        const int dg0 = t >> 6;  // 0..3
#pragma unroll
        for (int it = 0; it < 4; ++it) {
            int dg = dg0 + it * 4;                       // 0..15
            float4 q4 = *reinterpret_cast<const float4*>(Qh + (size_t)(q0 + rr) * HDIM + dg * 4);
            Qs[dg * 4 + 0][rr] = q4.x;
            Qs[dg * 4 + 1][rr] = q4.y;
            Qs[dg * 4 + 2][rr] = q4.z;
            Qs[dg * 4 + 3][rr] = q4.w;
        }
    }

    const float scale = 0.125f;  // 1/sqrt(64)
    float m[4], l[4], acc[4][4];
#pragma unroll
    for (int i = 0; i < 4; ++i) {
        m[i] = -1e30f;
        l[i] = 0.0f;
#pragma unroll
        for (int j = 0; j < 4; ++j) acc[i][j] = 0.0f;
    }

    const int nkt = blockIdx.x + 1;  // causal
    for (int kt = 0; kt < nkt; ++kt) {
        const int k0 = kt * 64;
        __syncthreads();  // prior PV done with KVs/Ps; Q store visible (kt=0)

        // Load K transposed: KVs[d][c] = K[k0+c][d]
        {
            const int cc = t & 63;
            const int dg0 = t >> 6;
#pragma unroll
            for (int it = 0; it < 4; ++it) {
                int dg = dg0 + it * 4;
                float4 k4 = *reinterpret_cast<const float4*>(Kh + (size_t)(k0 + cc) * HDIM + dg * 4);
                KVs[dg * 4 + 0][cc] = k4.x;
                KVs[dg * 4 + 1][cc] = k4.y;
                KVs[dg * 4 + 2][cc] = k4.z;
                KVs[dg * 4 + 3][cc] = k4.w;
            }
        }
        __syncthreads();

        // Scores: s[i][j] = Q[r0+i,:] . K[k0+x0+j,:]
        float s[4][4];
#pragma unroll
        for (int i = 0; i < 4; ++i)
#pragma unroll
            for (int j = 0; j < 4; ++j) s[i][j] = 0.0f;

#pragma unroll 4
        for (int d = 0; d < 64; ++d) {
            float4 qv = *reinterpret_cast<const float4*>(&Qs[d][r0]);
            float4 kv = *reinterpret_cast<const float4*>(&KVs[d][x0]);
            s[0][0] += qv.x * kv.x; s[0][1] += qv.x * kv.y; s[0][2] += qv.x * kv.z; s[0][3] += qv.x * kv.w;
            s[1][0] += qv.y * kv.x; s[1][1] += qv.y * kv.y; s[1][2] += qv.y * kv.z; s[1][3] += qv.y * kv.w;
            s[2][0] += qv.z * kv.x; s[2][1] += qv.z * kv.y; s[2][2] += qv.z * kv.z; s[2][3] += qv.z * kv.w;
            s[3][0] += qv.w * kv.x; s[3][1] += qv.w * kv.y; s[3][2] += qv.w * kv.z; s[3][3] += qv.w * kv.w;
        }

#pragma unroll
        for (int i = 0; i < 4; ++i)
#pragma unroll
            for (int j = 0; j < 4; ++j) s[i][j] *= scale;

        if (kt == nkt - 1) {  // diagonal tile: causal mask
#pragma unroll
            for (int i = 0; i < 4; ++i)
#pragma unroll
                for (int j = 0; j < 4; ++j)
                    if (k0 + x0 + j > q0 + r0 + i) s[i][j] += MASK_NEG;
        }

        // Online softmax per row (reduce across the 16 tx lanes)
#pragma unroll
        for (int i = 0; i < 4; ++i) {
            float mt = fmaxf(fmaxf(s[i][0], s[i][1]), fmaxf(s[i][2], s[i][3]));
            mt = fmaxf(mt, __shfl_xor_sync(0xffffffffu, mt, 1));
            mt = fmaxf(mt, __shfl_xor_sync(0xffffffffu, mt, 2));
            mt = fmaxf(mt, __shfl_xor_sync(0xffffffffu, mt, 4));
            mt = fmaxf(mt, __shfl_xor_sync(0xffffffffu, mt, 8));

            float mnew = fmaxf(m[i], mt);
            float corr = __expf(m[i] - mnew);
            float ps = 0.0f;
#pragma unroll
            for (int j = 0; j < 4; ++j) {
                float p = __expf(s[i][j] - mnew);
                s[i][j] = p;
                ps += p;
            }
            ps += __shfl_xor_sync(0xffffffffu, ps, 1);
            ps += __shfl_xor_sync(0xffffffffu, ps, 2);
            ps += __shfl_xor_sync(0xffffffffu, ps, 4);
            ps += __shfl_xor_sync(0xffffffffu, ps, 8);
            l[i] = l[i] * corr + ps;
            m[i] = mnew;
#pragma unroll
            for (int j = 0; j < 4; ++j) acc[i][j] *= corr;
        }

        // Store P transposed with XOR swizzle: Ps[c][rows 4ty..4ty+3]
#pragma unroll
        for (int j = 0; j < 4; ++j) {
            int c = x0 + j;
            int pcol = ty ^ (c & 15);
            float4 p4 = make_float4(s[0][j], s[1][j], s[2][j], s[3][j]);
            *reinterpret_cast<float4*>(&Ps[c][pcol * 4]) = p4;
        }
        __syncthreads();  // P written; K reads done -> KVs reusable

        // Load V row-major: KVs[c][d] = V[k0+c][d]
        {
            const int row0 = t >> 4;        // 0..15
            const int dq = (t & 15) * 4;
#pragma unroll
            for (int it = 0; it < 4; ++it) {
                int row = row0 + it * 16;
                *reinterpret_cast<float4*>(&KVs[row][dq]) =
                    *reinterpret_cast<const float4*>(Vh + (size_t)(k0 + row) * HDIM + dq);
            }
        }
        __syncthreads();

        // PV: acc[i][j] += P[r0+i][c] * V[c][x0+j]
#pragma unroll 4
        for (int c = 0; c < 64; ++c) {
            int pcol = ty ^ (c & 15);
            float4 pv = *reinterpret_cast<const float4*>(&Ps[c][pcol * 4]);
            float4 vv = *reinterpret_cast<const float4*>(&KVs[c][x0]);
            acc[0][0] += pv.x * vv.x; acc[0][1] += pv.x * vv.y; acc[0][2] += pv.x * vv.z; acc[0][3] += pv.x * vv.w;
            acc[1][0] += pv.y * vv.x; acc[1][1] += pv.y * vv.y; acc[1][2] += pv.y * vv.z; acc[1][3] += pv.y * vv.w;
            acc[2][0] += pv.z * vv.x; acc[2][1] += pv.z * vv.y; acc[2][2] += pv.z * vv.z; acc[2][3] += pv.z * vv.w;
            acc[3][0] += pv.w * vv.x; acc[3][1] += pv.w * vv.y; acc[3][2] += pv.w * vv.z; acc[3][3] += pv.w * vv.w;
        }
    }

    // Normalize and write ctx[(q0+r)*B + b][h*64 + x0..x0+3]
    const int b = bh >> 5;
    const int h = bh & 31;
#pragma unroll
    for (int i = 0; i < 4; ++i) {
        float inv_l = 1.0f / l[i];
        int row = q0 + r0 + i;
        float4 o;
        o.x = acc[i][0] * inv_l;
        o.y = acc[i][1] * inv_l;
        o.z = acc[i][2] * inv_l;
        o.w = acc[i][3] * inv_l;
        *reinterpret_cast<float4*>(g_ctx + (size_t)(row * BATCH + b) * EMB + h * HDIM + x0) = o;
    }
}

// ---------------------------------------------------------------------------
// Launch
// ---------------------------------------------------------------------------
extern "C" void kernel_launch(void* const* d_in, const int* in_sizes, int n_in,
                              void* d_out, int out_size) {
    const float* hs    = (const float*)d_in[0];
    const float* qkv_w = (const float*)d_in[1];
    const float* qkv_b = (const float*)d_in[2];
    const float* out_w = (const float*)d_in[3];
    const float* out_b = (const float*)d_in[4];
    float* out = (float*)d_out;

    float *qkv, *ctx;
    cudaGetSymbolAddress((void**)&qkv, g_qkv);
    cudaGetSymbolAddress((void**)&ctx, g_ctx);

    // 1. QKV projection
    {
        dim3 grid(QKV_N / 128, MROWS / 128);
        sgemm_bias<128, 128, 8, 8, 8><<<grid, 256>>>(MROWS, QKV_N, EMB,
                                                     hs, qkv_w, qkv_b, qkv);
    }

    // 2. RoPE + split
    rope_split_kernel<<<(S_LEN * BATCH * HEADS * HDIM) / 256, 256>>>();

    // 3. Causal attention
    {
        dim3 grid(S_LEN / 64, BATCH * HEADS);
        attn_kernel<<<grid, 256>>>();
    }

    // 4. Output projection
    {
        dim3 grid(EMB / 128, MROWS / 128);
        sgemm_bias<128, 128, 8, 8, 8><<<grid, 256>>>(MROWS, EMB, EMB,
                                                     ctx, out_w, out_b, out);
    }
}

// round 4
// speedup vs baseline: 2.8435x; 1.5338x over previous
#include <cuda_runtime.h>
#include <cuda_bf16.h>
#include <math.h>
#include <stdint.h>

// Problem constants
#define S_LEN 2048
#define BATCH 2
#define EMB   2048
#define HEADS 32
#define HDIM  64
#define MROWS (S_LEN * BATCH)          // 4096
#define QKV_N (3 * EMB)                // 6144
#define K3    6144                     // expanded K: [hi | lo | hi]
#define NIT   96                       // K3 / 64
#define MASK_NEG (-66504.0f)

// ---------------------------------------------------------------------------
// Scratch (static device globals)
// ---------------------------------------------------------------------------
__device__ float g_qkv[(size_t)MROWS * QKV_N];                 // [4096, 6144]
__device__ float g_q  [(size_t)BATCH * HEADS * S_LEN * HDIM];
__device__ float g_k  [(size_t)BATCH * HEADS * S_LEN * HDIM];
__device__ float g_v  [(size_t)BATCH * HEADS * S_LEN * HDIM];
__device__ float g_ctx[(size_t)MROWS * EMB];                   // [4096, 2048]

__device__ __nv_bfloat16 g_A3 [(size_t)MROWS * K3];            // activations (hi|lo|hi)
__device__ __nv_bfloat16 g_B3q[(size_t)QKV_N * K3];            // qkv_w^T   (hi|hi|lo)
__device__ __nv_bfloat16 g_B3o[(size_t)EMB   * K3];            // out_w^T   (hi|hi|lo)

// ---------------------------------------------------------------------------
// Helpers (all sm_80-era PTX — legal at compute_103)
// ---------------------------------------------------------------------------
__device__ __forceinline__ uint32_t smem_u32(const void* p) {
    uint32_t a;
    asm("{ .reg .u64 t; cvta.to.shared.u64 t, %1; cvt.u32.u64 %0, t; }" : "=r"(a) : "l"(p));
    return a;
}
__device__ __forceinline__ void cp16(uint32_t saddr, const void* g) {
    asm volatile("cp.async.cg.shared.global [%0], [%1], 16;" :: "r"(saddr), "l"(g) : "memory");
}
__device__ __forceinline__ void cp_commit() {
    asm volatile("cp.async.commit_group;" ::: "memory");
}
__device__ __forceinline__ uint32_t sw128(uint32_t off) {
    return off ^ ((off >> 3) & 0x70);
}

#define LDSM4(r, addr) \
    asm volatile("ldmatrix.sync.aligned.m8n8.x4.shared.b16 {%0,%1,%2,%3}, [%4];" \
                 : "=r"((r)[0]), "=r"((r)[1]), "=r"((r)[2]), "=r"((r)[3]) : "r"(addr))

__device__ __forceinline__ void mma_bf16(float* d, const uint32_t* a, uint32_t b0, uint32_t b1) {
    asm volatile(
        "mma.sync.aligned.m16n8k16.row.col.f32.bf16.bf16.f32 "
        "{%0,%1,%2,%3}, {%4,%5,%6,%7}, {%8,%9}, {%0,%1,%2,%3};"
        : "+f"(d[0]), "+f"(d[1]), "+f"(d[2]), "+f"(d[3])
        : "r"(a[0]), "r"(a[1]), "r"(a[2]), "r"(a[3]), "r"(b0), "r"(b1));
}

// ---------------------------------------------------------------------------
// HMMA split-bf16 GEMM:  C[M=4096, N] = A3[M, K3] @ B3[N, K3]^T + bias
// CTA tile 128x128, BK=64, 3-stage cp.async pipeline (96KB dyn smem).
// 8 warps (2 m x 4 n), each warp 64x32 via mma.m16n8k16.
// ---------------------------------------------------------------------------
#define GEMM_SMEM (3 * 32768)

__global__ __launch_bounds__(256)
void gemm_mma_bf16(int N,
                   const __nv_bfloat16* __restrict__ A3,
                   const __nv_bfloat16* __restrict__ B3,
                   const float* __restrict__ bias,
                   float* __restrict__ C) {
    extern __shared__ char sm[];
    const int tid = threadIdx.x;
    const int wid = tid >> 5;
    const int lid = tid & 31;
    const int M0 = blockIdx.y * 128;
    const int N0 = blockIdx.x * 128;
    const uint32_t sbase = smem_u32(sm);

    // loader: 2 threads per 128B row; 4x16B each
    const int lrow  = tid >> 1;
    const int lhalf = (tid & 1) * 64;
    const uint32_t soff = (uint32_t)lrow * 128u + (uint32_t)lhalf;
    const char* Ag = (const char*)(A3 + (size_t)(M0 + lrow) * K3) + lhalf;
    const char* Bg = (const char*)(B3 + (size_t)(N0 + lrow) * K3) + lhalf;

    // warp tiling: wm in {0,64}, wn in {0,32,64,96}
    const int wm = (wid & 1) * 64;
    const int wn = (wid >> 1) * 32;
    // ldmatrix lane geometry
    const int a_r  = wm + (lid & 15);          // A row within tile
    const int a_cb = (lid >> 4) * 16;          // A byte offset within k16 (0 or 16)
    const int b_r  = wn + (lid & 7) + ((lid >> 4) << 3);  // B (n) row
    const int b_cb = ((lid >> 3) & 1) * 16;    // B byte offset within k16

    float acc[4][4][4];
#pragma unroll
    for (int i = 0; i < 4; ++i)
#pragma unroll
        for (int j = 0; j < 4; ++j)
#pragma unroll
            for (int q = 0; q < 4; ++q) acc[i][j][q] = 0.0f;

    // prologue: stages 0,1
#pragma unroll
    for (int s = 0; s < 2; ++s) {
        uint32_t ab = sbase + s * 32768u;
        uint32_t bb = ab + 16384u;
        const char* ag = Ag + s * 128;
        const char* bg = Bg + s * 128;
#pragma unroll
        for (int i = 0; i < 4; ++i) {
            cp16(ab + sw128(soff + i * 16), ag + i * 16);
            cp16(bb + sw128(soff + i * 16), bg + i * 16);
        }
        cp_commit();
    }

#pragma unroll 1
    for (int it = 0; it < NIT; ++it) {
        if (it + 1 < NIT) asm volatile("cp.async.wait_group 1;" ::: "memory");
        else              asm volatile("cp.async.wait_group 0;" ::: "memory");
        __syncthreads();

        // prefetch stage it+2 (overwrites stage consumed at iter it-1)
        if (it + 2 < NIT) {
            int s1 = (it + 2) % 3;
            uint32_t ab = sbase + s1 * 32768u;
            uint32_t bb = ab + 16384u;
            const char* ag = Ag + (size_t)(it + 2) * 128;
            const char* bg = Bg + (size_t)(it + 2) * 128;
#pragma unroll
            for (int i = 0; i < 4; ++i) {
                cp16(ab + sw128(soff + i * 16), ag + i * 16);
                cp16(bb + sw128(soff + i * 16), bg + i * 16);
            }
            cp_commit();
        }

        const int s = it % 3;
        const uint32_t ab = sbase + s * 32768u;
        const uint32_t bb = ab + 16384u;

#pragma unroll
        for (int kk = 0; kk < 4; ++kk) {
            uint32_t Ar[4][4];
            uint32_t Br[2][4];
#pragma unroll
            for (int i = 0; i < 4; ++i)
                LDSM4(Ar[i], ab + sw128((uint32_t)(a_r + i * 16) * 128u + kk * 32 + a_cb));
#pragma unroll
            for (int j2 = 0; j2 < 2; ++j2)
                LDSM4(Br[j2], bb + sw128((uint32_t)(b_r + j2 * 16) * 128u + kk * 32 + b_cb));
#pragma unroll
            for (int i = 0; i < 4; ++i)
#pragma unroll
                for (int j = 0; j < 4; ++j)
                    mma_bf16(acc[i][j], Ar[i], Br[j >> 1][(j & 1) * 2], Br[j >> 1][(j & 1) * 2 + 1]);
        }
    }

    // epilogue: fragment layout m16n8 -> rows (lid>>2, +8), cols (lid&3)*2
    const int fr = lid >> 2;
    const int fc = (lid & 3) * 2;
#pragma unroll
    for (int j = 0; j < 4; ++j) {
        const int col = N0 + wn + j * 8 + fc;
        const float bx = bias[col];
        const float by = bias[col + 1];
#pragma unroll
        for (int i = 0; i < 4; ++i) {
            const int row = M0 + wm + i * 16 + fr;
            float2 v0 = make_float2(acc[i][j][0] + bx, acc[i][j][1] + by);
            float2 v1 = make_float2(acc[i][j][2] + bx, acc[i][j][3] + by);
            *reinterpret_cast<float2*>(C + (size_t)row * N + col) = v0;
            *reinterpret_cast<float2*>(C + (size_t)(row + 8) * N + col) = v1;
        }
    }
}

// ---------------------------------------------------------------------------
// Conversions
// ---------------------------------------------------------------------------
// A: fp32 [M,2048] -> bf16 [M, 6144] as (hi | lo | hi)
__global__ __launch_bounds__(256)
void convA_kernel(const float* __restrict__ src, __nv_bfloat16* __restrict__ dst) {
    int i = blockIdx.x * 256 + threadIdx.x;   // M*512 threads
    int m = i >> 9;
    int j = (i & 511) * 4;
    float4 a = *reinterpret_cast<const float4*>(src + (size_t)m * EMB + j);
    float v[4] = {a.x, a.y, a.z, a.w};
    __nv_bfloat16 h[4], l[4];
#pragma unroll
    for (int q = 0; q < 4; ++q) {
        h[q] = __float2bfloat16(v[q]);
        l[q] = __float2bfloat16(v[q] - __bfloat162float(h[q]));
    }
    __nv_bfloat16* d0 = dst + (size_t)m * K3 + j;
    __nv_bfloat162 h01 = __halves2bfloat162(h[0], h[1]);
    __nv_bfloat162 h23 = __halves2bfloat162(h[2], h[3]);
    __nv_bfloat162 l01 = __halves2bfloat162(l[0], l[1]);
    __nv_bfloat162 l23 = __halves2bfloat162(l[2], l[3]);
    *reinterpret_cast<__nv_bfloat162*>(d0 + 0) = h01;
    *reinterpret_cast<__nv_bfloat162*>(d0 + 2) = h23;
    *reinterpret_cast<__nv_bfloat162*>(d0 + 2048 + 0) = l01;
    *reinterpret_cast<__nv_bfloat162*>(d0 + 2048 + 2) = l23;
    *reinterpret_cast<__nv_bfloat162*>(d0 + 4096 + 0) = h01;
    *reinterpret_cast<__nv_bfloat162*>(d0 + 4096 + 2) = h23;
}

// B: fp32 [2048, Ncols] -> transposed bf16 [Ncols, 6144] as (hi | hi | lo)
__global__ __launch_bounds__(1024)
void convB_kernel(const float* __restrict__ src, __nv_bfloat16* __restrict__ dst, int Ncols) {
    __shared__ float tile[32][33];
    const int k0 = blockIdx.y * 32;
    const int n0 = blockIdx.x * 32;
    const int tx = threadIdx.x;
    const int ty = threadIdx.y;
    tile[ty][tx] = src[(size_t)(k0 + ty) * Ncols + n0 + tx];
    __syncthreads();
    float v = tile[tx][ty];
    __nv_bfloat16 h = __float2bfloat16(v);
    __nv_bfloat16 lo = __float2bfloat16(v - __bfloat162float(h));
    size_t drow = (size_t)(n0 + ty) * K3 + k0 + tx;
    dst[drow + 0]    = h;
    dst[drow + 2048] = h;
    dst[drow + 4096] = lo;
}

// ---------------------------------------------------------------------------
// RoPE + split
// ---------------------------------------------------------------------------
__global__ __launch_bounds__(256)
void rope_split_kernel() {
    int idx = blockIdx.x * blockDim.x + threadIdx.x;
    int d = idx & 63;
    int h = (idx >> 6) & 31;
    int b = (idx >> 11) & 1;
    int s = idx >> 12;

    const float* base = g_qkv + (size_t)(s * BATCH + b) * QKV_N;
    int col = h * HDIM + d;

    float qv = base[col];
    float kv = base[EMB + col];
    float vv = base[2 * EMB + col];

    int i = d & 31;
    float inv_freq = __expf(-0.28782252f * (float)i);
    float ang = (float)s * inv_freq;
    float sn, cs;
    sincosf(ang, &sn, &cs);

    float qpair, kpair;
    if (d < 32) {
        qpair = -base[col + 32];
        kpair = -base[EMB + col + 32];
    } else {
        qpair = base[col - 32];
        kpair = base[EMB + col - 32];
    }

    size_t o = ((size_t)(b * HEADS + h) * S_LEN + s) * HDIM + d;
    g_q[o] = qv * cs + qpair * sn;
    g_k[o] = kv * cs + kpair * sn;
    g_v[o] = vv;
}

// ---------------------------------------------------------------------------
// Causal flash attention (register-blocked, unchanged from round 2)
// ---------------------------------------------------------------------------
__global__ __launch_bounds__(256)
void attn_kernel() {
    __shared__ float Qs[64][64];
    __shared__ float KVs[64][64];
    __shared__ float Ps[64][64];

    const int bh = blockIdx.y;
    const int q0 = blockIdx.x * 64;
    const int t  = threadIdx.x;
    const int ty = t >> 4;
    const int tx = t & 15;
    const int r0 = ty * 4;
    const int x0 = tx * 4;

    const float* Qh = g_q + (size_t)bh * S_LEN * HDIM;
    const float* Kh = g_k + (size_t)bh * S_LEN * HDIM;
    const float* Vh = g_v + (size_t)bh * S_LEN * HDIM;

    {
        const int rr = t & 63;
        const int dg0 = t >> 6;
#pragma unroll
        for (int it = 0; it < 4; ++it) {
            int dg = dg0 + it * 4;
            float4 q4 = *reinterpret_cast<const float4*>(Qh + (size_t)(q0 + rr) * HDIM + dg * 4);
            Qs[dg * 4 + 0][rr] = q4.x;
            Qs[dg * 4 + 1][rr] = q4.y;
            Qs[dg * 4 + 2][rr] = q4.z;
            Qs[dg * 4 + 3][rr] = q4.w;
        }
    }

    const float scale = 0.125f;
    float m[4], l[4], acc[4][4];
#pragma unroll
    for (int i = 0; i < 4; ++i) {
        m[i] = -1e30f;
        l[i] = 0.0f;
#pragma unroll
        for (int j = 0; j < 4; ++j) acc[i][j] = 0.0f;
    }

    const int nkt = blockIdx.x + 1;
    for (int kt = 0; kt < nkt; ++kt) {
        const int k0 = kt * 64;
        __syncthreads();

        {
            const int cc = t & 63;
            const int dg0 = t >> 6;
#pragma unroll
            for (int it = 0; it < 4; ++it) {
                int dg = dg0 + it * 4;
                float4 k4 = *reinterpret_cast<const float4*>(Kh + (size_t)(k0 + cc) * HDIM + dg * 4);
                KVs[dg * 4 + 0][cc] = k4.x;
                KVs[dg * 4 + 1][cc] = k4.y;
                KVs[dg * 4 + 2][cc] = k4.z;
                KVs[dg * 4 + 3][cc] = k4.w;
            }
        }
        __syncthreads();

        float s[4][4];
#pragma unroll
        for (int i = 0; i < 4; ++i)
#pragma unroll
            for (int j = 0; j < 4; ++j) s[i][j] = 0.0f;

#pragma unroll 4
        for (int d = 0; d < 64; ++d) {
            float4 qv = *reinterpret_cast<const float4*>(&Qs[d][r0]);
            float4 kv = *reinterpret_cast<const float4*>(&KVs[d][x0]);
            s[0][0] += qv.x * kv.x; s[0][1] += qv.x * kv.y; s[0][2] += qv.x * kv.z; s[0][3] += qv.x * kv.w;
            s[1][0] += qv.y * kv.x; s[1][1] += qv.y * kv.y; s[1][2] += qv.y * kv.z; s[1][3] += qv.y * kv.w;
            s[2][0] += qv.z * kv.x; s[2][1] += qv.z * kv.y; s[2][2] += qv.z * kv.z; s[2][3] += qv.z * kv.w;
            s[3][0] += qv.w * kv.x; s[3][1] += qv.w * kv.y; s[3][2] += qv.w * kv.z; s[3][3] += qv.w * kv.w;
        }

#pragma unroll
        for (int i = 0; i < 4; ++i)
#pragma unroll
            for (int j = 0; j < 4; ++j) s[i][j] *= scale;

        if (kt == nkt - 1) {
#pragma unroll
            for (int i = 0; i < 4; ++i)
#pragma unroll
                for (int j = 0; j < 4; ++j)
                    if (k0 + x0 + j > q0 + r0 + i) s[i][j] += MASK_NEG;
        }

#pragma unroll
        for (int i = 0; i < 4; ++i) {
            float mt = fmaxf(fmaxf(s[i][0], s[i][1]), fmaxf(s[i][2], s[i][3]));
            mt = fmaxf(mt, __shfl_xor_sync(0xffffffffu, mt, 1));
            mt = fmaxf(mt, __shfl_xor_sync(0xffffffffu, mt, 2));
            mt = fmaxf(mt, __shfl_xor_sync(0xffffffffu, mt, 4));
            mt = fmaxf(mt, __shfl_xor_sync(0xffffffffu, mt, 8));

            float mnew = fmaxf(m[i], mt);
            float corr = __expf(m[i] - mnew);
            float ps = 0.0f;
#pragma unroll
            for (int j = 0; j < 4; ++j) {
                float p = __expf(s[i][j] - mnew);
                s[i][j] = p;
                ps += p;
            }
            ps += __shfl_xor_sync(0xffffffffu, ps, 1);
            ps += __shfl_xor_sync(0xffffffffu, ps, 2);
            ps += __shfl_xor_sync(0xffffffffu, ps, 4);
            ps += __shfl_xor_sync(0xffffffffu, ps, 8);
            l[i] = l[i] * corr + ps;
            m[i] = mnew;
#pragma unroll
            for (int j = 0; j < 4; ++j) acc[i][j] *= corr;
        }

#pragma unroll
        for (int j = 0; j < 4; ++j) {
            int c = x0 + j;
            int pcol = ty ^ (c & 15);
            float4 p4 = make_float4(s[0][j], s[1][j], s[2][j], s[3][j]);
            *reinterpret_cast<float4*>(&Ps[c][pcol * 4]) = p4;
        }
        __syncthreads();

        {
            const int row0 = t >> 4;
            const int dq = (t & 15) * 4;
#pragma unroll
            for (int it = 0; it < 4; ++it) {
                int row = row0 + it * 16;
                *reinterpret_cast<float4*>(&KVs[row][dq]) =
                    *reinterpret_cast<const float4*>(Vh + (size_t)(k0 + row) * HDIM + dq);
            }
        }
        __syncthreads();

#pragma unroll 4
        for (int c = 0; c < 64; ++c) {
            int pcol = ty ^ (c & 15);
            float4 pv = *reinterpret_cast<const float4*>(&Ps[c][pcol * 4]);
            float4 vv = *reinterpret_cast<const float4*>(&KVs[c][x0]);
            acc[0][0] += pv.x * vv.x; acc[0][1] += pv.x * vv.y; acc[0][2] += pv.x * vv.z; acc[0][3] += pv.x * vv.w;
            acc[1][0] += pv.y * vv.x; acc[1][1] += pv.y * vv.y; acc[1][2] += pv.y * vv.z; acc[1][3] += pv.y * vv.w;
            acc[2][0] += pv.z * vv.x; acc[2][1] += pv.z * vv.y; acc[2][2] += pv.z * vv.z; acc[2][3] += pv.z * vv.w;
            acc[3][0] += pv.w * vv.x; acc[3][1] += pv.w * vv.y; acc[3][2] += pv.w * vv.z; acc[3][3] += pv.w * vv.w;
        }
    }

    const int b = bh >> 5;
    const int h = bh & 31;
#pragma unroll
    for (int i = 0; i < 4; ++i) {
        float inv_l = 1.0f / l[i];
        int row = q0 + r0 + i;
        float4 o;
        o.x = acc[i][0] * inv_l;
        o.y = acc[i][1] * inv_l;
        o.z = acc[i][2] * inv_l;
        o.w = acc[i][3] * inv_l;
        *reinterpret_cast<float4*>(g_ctx + (size_t)(row * BATCH + b) * EMB + h * HDIM + x0) = o;
    }
}

// ---------------------------------------------------------------------------
// Launch
// ---------------------------------------------------------------------------
extern "C" void kernel_launch(void* const* d_in, const int* in_sizes, int n_in,
                              void* d_out, int out_size) {
    const float* hs    = (const float*)d_in[0];
    const float* qkv_w = (const float*)d_in[1];
    const float* qkv_b = (const float*)d_in[2];
    const float* out_w = (const float*)d_in[3];
    const float* out_b = (const float*)d_in[4];
    float* out = (float*)d_out;

    cudaFuncSetAttribute(gemm_mma_bf16, cudaFuncAttributeMaxDynamicSharedMemorySize, GEMM_SMEM);

    float *qkv, *ctx;
    __nv_bfloat16 *A3, *B3q, *B3o;
    cudaGetSymbolAddress((void**)&qkv, g_qkv);
    cudaGetSymbolAddress((void**)&ctx, g_ctx);
    cudaGetSymbolAddress((void**)&A3,  g_A3);
    cudaGetSymbolAddress((void**)&B3q, g_B3q);
    cudaGetSymbolAddress((void**)&B3o, g_B3o);

    // Weight conversions (transpose + hi/lo split)
    {
        dim3 blk(32, 32);
        convB_kernel<<<dim3(QKV_N / 32, EMB / 32), blk>>>(qkv_w, B3q, QKV_N);
        convB_kernel<<<dim3(EMB / 32, EMB / 32), blk>>>(out_w, B3o, EMB);
    }
    // Activation conversion
    convA_kernel<<<MROWS * 512 / 256, 256>>>(hs, A3);

    // 1. QKV projection (HMMA)
    gemm_mma_bf16<<<dim3(QKV_N / 128, MROWS / 128), 256, GEMM_SMEM>>>(QKV_N, A3, B3q, qkv_b, qkv);

    // 2. RoPE + split
    rope_split_kernel<<<(S_LEN * BATCH * HEADS * HDIM) / 256, 256>>>();

    // 3. Causal attention
    attn_kernel<<<dim3(S_LEN / 64, BATCH * HEADS), 256>>>();

    // 4. ctx conversion + output projection (HMMA)
    convA_kernel<<<MROWS * 512 / 256, 256>>>(ctx, A3);
    gemm_mma_bf16<<<dim3(EMB / 128, MROWS / 128), 256, GEMM_SMEM>>>(EMB, A3, B3o, out_b, out);
}

// round 5
// speedup vs baseline: 3.2470x; 1.1419x over previous
#include <cuda_runtime.h>
#include <cuda_bf16.h>
#include <math.h>
#include <stdint.h>

// Problem constants
#define S_LEN 2048
#define BATCH 2
#define EMB   2048
#define HEADS 32
#define HDIM  64
#define MROWS (S_LEN * BATCH)          // 4096
#define QKV_N (3 * EMB)                // 6144
#define K3    6144                     // expanded K: [hi | lo | hi]
#define NIT   96                       // K3 / 64
#define MASK_NEG (-66504.0f)

// ---------------------------------------------------------------------------
// Scratch (static device globals)
// ---------------------------------------------------------------------------
__device__ float g_qkv[(size_t)MROWS * QKV_N];                 // [4096, 6144]
__device__ float g_q  [(size_t)BATCH * HEADS * S_LEN * HDIM];
__device__ float g_k  [(size_t)BATCH * HEADS * S_LEN * HDIM];
__device__ float g_v  [(size_t)BATCH * HEADS * S_LEN * HDIM];
__device__ float g_ctx[(size_t)MROWS * EMB];                   // [4096, 2048]

__device__ __nv_bfloat16 g_A3 [(size_t)MROWS * K3];            // activations (hi|lo|hi)
__device__ __nv_bfloat16 g_B3q[(size_t)QKV_N * K3];            // qkv_w^T   (hi|hi|lo)
__device__ __nv_bfloat16 g_B3o[(size_t)EMB   * K3];            // out_w^T   (hi|hi|lo)

// ---------------------------------------------------------------------------
// Helpers (sm_80-era PTX — legal at compute_103)
// ---------------------------------------------------------------------------
__device__ __forceinline__ uint32_t smem_u32(const void* p) {
    uint32_t a;
    asm("{ .reg .u64 t; cvta.to.shared.u64 t, %1; cvt.u32.u64 %0, t; }" : "=r"(a) : "l"(p));
    return a;
}
__device__ __forceinline__ void cp16(uint32_t saddr, const void* g) {
    asm volatile("cp.async.cg.shared.global [%0], [%1], 16;" :: "r"(saddr), "l"(g) : "memory");
}
__device__ __forceinline__ void cp_commit() {
    asm volatile("cp.async.commit_group;" ::: "memory");
}
__device__ __forceinline__ uint32_t sw128(uint32_t off) {
    return off ^ ((off >> 3) & 0x70);
}

#define LDSM4(r, addr) \
    asm volatile("ldmatrix.sync.aligned.m8n8.x4.shared.b16 {%0,%1,%2,%3}, [%4];" \
                 : "=r"((r)[0]), "=r"((r)[1]), "=r"((r)[2]), "=r"((r)[3]) : "r"(addr))

__device__ __forceinline__ void mma_bf16(float* d, const uint32_t* a, uint32_t b0, uint32_t b1) {
    asm volatile(
        "mma.sync.aligned.m16n8k16.row.col.f32.bf16.bf16.f32 "
        "{%0,%1,%2,%3}, {%4,%5,%6,%7}, {%8,%9}, {%0,%1,%2,%3};"
        : "+f"(d[0]), "+f"(d[1]), "+f"(d[2]), "+f"(d[3])
        : "r"(a[0]), "r"(a[1]), "r"(a[2]), "r"(a[3]), "r"(b0), "r"(b1));
}

// ---------------------------------------------------------------------------
// HMMA split-bf16 GEMM:  C[M=4096, N] = A3[M, K3] @ B3[N, K3]^T + bias
// CTA tile 128x128, BK=64, 3-stage cp.async pipeline, 2 CTAs/SM.
// ---------------------------------------------------------------------------
#define GEMM_SMEM (3 * 32768)

__global__ __launch_bounds__(256, 2)
void gemm_mma_bf16(int N,
                   const __nv_bfloat16* __restrict__ A3,
                   const __nv_bfloat16* __restrict__ B3,
                   const float* __restrict__ bias,
                   float* __restrict__ C) {
    extern __shared__ char sm[];
    const int tid = threadIdx.x;
    const int wid = tid >> 5;
    const int lid = tid & 31;
    const int M0 = blockIdx.y * 128;
    const int N0 = blockIdx.x * 128;
    const uint32_t sbase = smem_u32(sm);

    // loader: 2 threads per 128B row; 4x16B each
    const int lrow  = tid >> 1;
    const int lhalf = (tid & 1) * 64;
    const uint32_t soff = (uint32_t)lrow * 128u + (uint32_t)lhalf;
    const char* Ag = (const char*)(A3 + (size_t)(M0 + lrow) * K3) + lhalf;
    const char* Bg = (const char*)(B3 + (size_t)(N0 + lrow) * K3) + lhalf;

    // warp tiling: wm in {0,64}, wn in {0,32,64,96}
    const int wm = (wid & 1) * 64;
    const int wn = (wid >> 1) * 32;
    const int a_r  = wm + (lid & 15);
    const int a_cb = (lid >> 4) * 16;
    const int b_r  = wn + (lid & 7) + ((lid >> 4) << 3);
    const int b_cb = ((lid >> 3) & 1) * 16;

    float acc[4][4][4];
#pragma unroll
    for (int i = 0; i < 4; ++i)
#pragma unroll
        for (int j = 0; j < 4; ++j)
#pragma unroll
            for (int q = 0; q < 4; ++q) acc[i][j][q] = 0.0f;

    // prologue: stages 0,1
#pragma unroll
    for (int s = 0; s < 2; ++s) {
        uint32_t ab = sbase + s * 32768u;
        uint32_t bb = ab + 16384u;
        const char* ag = Ag + s * 128;
        const char* bg = Bg + s * 128;
#pragma unroll
        for (int i = 0; i < 4; ++i) {
            cp16(ab + sw128(soff + i * 16), ag + i * 16);
            cp16(bb + sw128(soff + i * 16), bg + i * 16);
        }
        cp_commit();
    }

#pragma unroll 1
    for (int it = 0; it < NIT; ++it) {
        if (it + 1 < NIT) asm volatile("cp.async.wait_group 1;" ::: "memory");
        else              asm volatile("cp.async.wait_group 0;" ::: "memory");
        __syncthreads();

        if (it + 2 < NIT) {
            int s1 = (it + 2) % 3;
            uint32_t ab = sbase + s1 * 32768u;
            uint32_t bb = ab + 16384u;
            const char* ag = Ag + (size_t)(it + 2) * 128;
            const char* bg = Bg + (size_t)(it + 2) * 128;
#pragma unroll
            for (int i = 0; i < 4; ++i) {
                cp16(ab + sw128(soff + i * 16), ag + i * 16);
                cp16(bb + sw128(soff + i * 16), bg + i * 16);
            }
            cp_commit();
        }

        const int s = it % 3;
        const uint32_t ab = sbase + s * 32768u;
        const uint32_t bb = ab + 16384u;

#pragma unroll
        for (int kk = 0; kk < 4; ++kk) {
            uint32_t Ar[4][4];
            uint32_t Br[2][4];
#pragma unroll
            for (int i = 0; i < 4; ++i)
                LDSM4(Ar[i], ab + sw128((uint32_t)(a_r + i * 16) * 128u + kk * 32 + a_cb));
#pragma unroll
            for (int j2 = 0; j2 < 2; ++j2)
                LDSM4(Br[j2], bb + sw128((uint32_t)(b_r + j2 * 16) * 128u + kk * 32 + b_cb));
#pragma unroll
            for (int i = 0; i < 4; ++i)
#pragma unroll
                for (int j = 0; j < 4; ++j)
                    mma_bf16(acc[i][j], Ar[i], Br[j >> 1][(j & 1) * 2], Br[j >> 1][(j & 1) * 2 + 1]);
        }
    }

    const int fr = lid >> 2;
    const int fc = (lid & 3) * 2;
#pragma unroll
    for (int j = 0; j < 4; ++j) {
        const int col = N0 + wn + j * 8 + fc;
        const float bx = bias[col];
        const float by = bias[col + 1];
#pragma unroll
        for (int i = 0; i < 4; ++i) {
            const int row = M0 + wm + i * 16 + fr;
            float2 v0 = make_float2(acc[i][j][0] + bx, acc[i][j][1] + by);
            float2 v1 = make_float2(acc[i][j][2] + bx, acc[i][j][3] + by);
            *reinterpret_cast<float2*>(C + (size_t)row * N + col) = v0;
            *reinterpret_cast<float2*>(C + (size_t)(row + 8) * N + col) = v1;
        }
    }
}

// ---------------------------------------------------------------------------
// Conversions
// ---------------------------------------------------------------------------
__global__ __launch_bounds__(256)
void convA_kernel(const float* __restrict__ src, __nv_bfloat16* __restrict__ dst) {
    int i = blockIdx.x * 256 + threadIdx.x;
    int m = i >> 9;
    int j = (i & 511) * 4;
    float4 a = *reinterpret_cast<const float4*>(src + (size_t)m * EMB + j);
    float v[4] = {a.x, a.y, a.z, a.w};
    __nv_bfloat16 h[4], l[4];
#pragma unroll
    for (int q = 0; q < 4; ++q) {
        h[q] = __float2bfloat16(v[q]);
        l[q] = __float2bfloat16(v[q] - __bfloat162float(h[q]));
    }
    __nv_bfloat16* d0 = dst + (size_t)m * K3 + j;
    __nv_bfloat162 h01 = __halves2bfloat162(h[0], h[1]);
    __nv_bfloat162 h23 = __halves2bfloat162(h[2], h[3]);
    __nv_bfloat162 l01 = __halves2bfloat162(l[0], l[1]);
    __nv_bfloat162 l23 = __halves2bfloat162(l[2], l[3]);
    *reinterpret_cast<__nv_bfloat162*>(d0 + 0) = h01;
    *reinterpret_cast<__nv_bfloat162*>(d0 + 2) = h23;
    *reinterpret_cast<__nv_bfloat162*>(d0 + 2048 + 0) = l01;
    *reinterpret_cast<__nv_bfloat162*>(d0 + 2048 + 2) = l23;
    *reinterpret_cast<__nv_bfloat162*>(d0 + 4096 + 0) = h01;
    *reinterpret_cast<__nv_bfloat162*>(d0 + 4096 + 2) = h23;
}

__global__ __launch_bounds__(1024)
void convB_kernel(const float* __restrict__ src, __nv_bfloat16* __restrict__ dst, int Ncols) {
    __shared__ float tile[32][33];
    const int k0 = blockIdx.y * 32;
    const int n0 = blockIdx.x * 32;
    const int tx = threadIdx.x;
    const int ty = threadIdx.y;
    tile[ty][tx] = src[(size_t)(k0 + ty) * Ncols + n0 + tx];
    __syncthreads();
    float v = tile[tx][ty];
    __nv_bfloat16 h = __float2bfloat16(v);
    __nv_bfloat16 lo = __float2bfloat16(v - __bfloat162float(h));
    size_t drow = (size_t)(n0 + ty) * K3 + k0 + tx;
    dst[drow + 0]    = h;
    dst[drow + 2048] = h;
    dst[drow + 4096] = lo;
}

// ---------------------------------------------------------------------------
// RoPE + split
// ---------------------------------------------------------------------------
__global__ __launch_bounds__(256)
void rope_split_kernel() {
    int idx = blockIdx.x * blockDim.x + threadIdx.x;
    int d = idx & 63;
    int h = (idx >> 6) & 31;
    int b = (idx >> 11) & 1;
    int s = idx >> 12;

    const float* base = g_qkv + (size_t)(s * BATCH + b) * QKV_N;
    int col = h * HDIM + d;

    float qv = base[col];
    float kv = base[EMB + col];
    float vv = base[2 * EMB + col];

    int i = d & 31;
    float inv_freq = __expf(-0.28782252f * (float)i);
    float ang = (float)s * inv_freq;
    float sn, cs;
    sincosf(ang, &sn, &cs);

    float qpair, kpair;
    if (d < 32) {
        qpair = -base[col + 32];
        kpair = -base[EMB + col + 32];
    } else {
        qpair = base[col - 32];
        kpair = base[EMB + col - 32];
    }

    size_t o = ((size_t)(b * HEADS + h) * S_LEN + s) * HDIM + d;
    g_q[o] = qv * cs + qpair * sn;
    g_k[o] = kv * cs + kpair * sn;
    g_v[o] = vv;
}

// ---------------------------------------------------------------------------
// Causal flash attention v3 — 128-query tile, 8x4 per-thread register tile.
// Grid: (16, B*H). 256 threads: ty=t>>4 owns rows 8ty..8ty+7, tx=t&15 owns
// 4 cols. Dyn smem 80KB: Qs[64][128] ([d][r]) + KVs[64][64] + Ps[64][128]
// (P transposed [c][r] with XOR swizzle on (c>>2)&15). 2 CTAs/SM.
// ---------------------------------------------------------------------------
#define ATTN_SMEM (80 * 1024)

__global__ __launch_bounds__(256, 2)
void attn_kernel() {
    extern __shared__ float smf[];
    float (*Qs)[128] = reinterpret_cast<float(*)[128]>(smf);                 // 32KB
    float (*KVs)[64] = reinterpret_cast<float(*)[64]>(smf + 8192);           // 16KB
    float (*Ps)[128] = reinterpret_cast<float(*)[128]>(smf + 8192 + 4096);   // 32KB

    const int bh = blockIdx.y;
    const int qt = (int)(gridDim.x - 1) - (int)blockIdx.x;  // longest-first
    const int q0 = qt * 128;
    const int t  = threadIdx.x;
    const int ty = t >> 4;     // 0..15
    const int tx = t & 15;     // 0..15
    const int r0 = ty * 8;
    const int x0 = tx * 4;

    const float* Qh = g_q + (size_t)bh * S_LEN * HDIM;
    const float* Kh = g_k + (size_t)bh * S_LEN * HDIM;
    const float* Vh = g_v + (size_t)bh * S_LEN * HDIM;

    // Load Q transposed: Qs[d][r], r in 0..127
    {
        const int rr = t & 127;
        const int dg0 = t >> 7;  // 0..1
#pragma unroll
        for (int it = 0; it < 8; ++it) {
            int dg = dg0 + it * 2;  // 0..15
            float4 q4 = *reinterpret_cast<const float4*>(Qh + (size_t)(q0 + rr) * HDIM + dg * 4);
            Qs[dg * 4 + 0][rr] = q4.x;
            Qs[dg * 4 + 1][rr] = q4.y;
            Qs[dg * 4 + 2][rr] = q4.z;
            Qs[dg * 4 + 3][rr] = q4.w;
        }
    }

    const float scale = 0.125f;
    float m[8], l[8], acc[8][4];
#pragma unroll
    for (int i = 0; i < 8; ++i) {
        m[i] = -1e30f;
        l[i] = 0.0f;
#pragma unroll
        for (int j = 0; j < 4; ++j) acc[i][j] = 0.0f;
    }

    const int nkt = 2 * qt + 2;
    for (int kt = 0; kt < nkt; ++kt) {
        const int k0 = kt * 64;
        __syncthreads();  // prior PV done with KVs/Ps; Q store visible (kt=0)

        // K tile transposed: KVs[d][c]
        {
            const int cc = t & 63;
            const int dg0 = t >> 6;
#pragma unroll
            for (int it = 0; it < 4; ++it) {
                int dg = dg0 + it * 4;
                float4 k4 = *reinterpret_cast<const float4*>(Kh + (size_t)(k0 + cc) * HDIM + dg * 4);
                KVs[dg * 4 + 0][cc] = k4.x;
                KVs[dg * 4 + 1][cc] = k4.y;
                KVs[dg * 4 + 2][cc] = k4.z;
                KVs[dg * 4 + 3][cc] = k4.w;
            }
        }
        __syncthreads();

        // Scores: s[i][j] = Q[r0+i,:] . K[k0+x0+j,:]
        float s[8][4];
#pragma unroll
        for (int i = 0; i < 8; ++i)
#pragma unroll
            for (int j = 0; j < 4; ++j) s[i][j] = 0.0f;

#pragma unroll 4
        for (int d = 0; d < 64; ++d) {
            float4 qa = *reinterpret_cast<const float4*>(&Qs[d][r0]);
            float4 qb = *reinterpret_cast<const float4*>(&Qs[d][r0 + 4]);
            float4 kv = *reinterpret_cast<const float4*>(&KVs[d][x0]);
            s[0][0] += qa.x * kv.x; s[0][1] += qa.x * kv.y; s[0][2] += qa.x * kv.z; s[0][3] += qa.x * kv.w;
            s[1][0] += qa.y * kv.x; s[1][1] += qa.y * kv.y; s[1][2] += qa.y * kv.z; s[1][3] += qa.y * kv.w;
            s[2][0] += qa.z * kv.x; s[2][1] += qa.z * kv.y; s[2][2] += qa.z * kv.z; s[2][3] += qa.z * kv.w;
            s[3][0] += qa.w * kv.x; s[3][1] += qa.w * kv.y; s[3][2] += qa.w * kv.z; s[3][3] += qa.w * kv.w;
            s[4][0] += qb.x * kv.x; s[4][1] += qb.x * kv.y; s[4][2] += qb.x * kv.z; s[4][3] += qb.x * kv.w;
            s[5][0] += qb.y * kv.x; s[5][1] += qb.y * kv.y; s[5][2] += qb.y * kv.z; s[5][3] += qb.y * kv.w;
            s[6][0] += qb.z * kv.x; s[6][1] += qb.z * kv.y; s[6][2] += qb.z * kv.z; s[6][3] += qb.z * kv.w;
            s[7][0] += qb.w * kv.x; s[7][1] += qb.w * kv.y; s[7][2] += qb.w * kv.z; s[7][3] += qb.w * kv.w;
        }

#pragma unroll
        for (int i = 0; i < 8; ++i)
#pragma unroll
            for (int j = 0; j < 4; ++j) s[i][j] *= scale;

        if (kt >= nkt - 2) {  // tiles overlapping the diagonal
#pragma unroll
            for (int i = 0; i < 8; ++i)
#pragma unroll
                for (int j = 0; j < 4; ++j)
                    if (k0 + x0 + j > q0 + r0 + i) s[i][j] += MASK_NEG;
        }

        // Online softmax per row (reduce across 16 tx lanes)
#pragma unroll
        for (int i = 0; i < 8; ++i) {
            float mt = fmaxf(fmaxf(s[i][0], s[i][1]), fmaxf(s[i][2], s[i][3]));
            mt = fmaxf(mt, __shfl_xor_sync(0xffffffffu, mt, 1));
            mt = fmaxf(mt, __shfl_xor_sync(0xffffffffu, mt, 2));
            mt = fmaxf(mt, __shfl_xor_sync(0xffffffffu, mt, 4));
            mt = fmaxf(mt, __shfl_xor_sync(0xffffffffu, mt, 8));

            float mnew = fmaxf(m[i], mt);
            float corr = __expf(m[i] - mnew);
            float ps = 0.0f;
#pragma unroll
            for (int j = 0; j < 4; ++j) {
                float p = __expf(s[i][j] - mnew);
                s[i][j] = p;
                ps += p;
            }
            ps += __shfl_xor_sync(0xffffffffu, ps, 1);
            ps += __shfl_xor_sync(0xffffffffu, ps, 2);
            ps += __shfl_xor_sync(0xffffffffu, ps, 4);
            ps += __shfl_xor_sync(0xffffffffu, ps, 8);
            l[i] = l[i] * corr + ps;
            m[i] = mnew;
#pragma unroll
            for (int j = 0; j < 4; ++j) acc[i][j] *= corr;
        }

        // Store P transposed with XOR swizzle keyed on (c>>2)&15
#pragma unroll
        for (int j = 0; j < 4; ++j) {
            int c = x0 + j;
            int ph = ty ^ ((c >> 2) & 15);
            float4 p0 = make_float4(s[0][j], s[1][j], s[2][j], s[3][j]);
            float4 p1 = make_float4(s[4][j], s[5][j], s[6][j], s[7][j]);
            *reinterpret_cast<float4*>(&Ps[c][ph * 8])     = p0;
            *reinterpret_cast<float4*>(&Ps[c][ph * 8 + 4]) = p1;
        }
        __syncthreads();  // P written; K reads done -> KVs reusable

        // V tile row-major: KVs[c][d]
        {
            const int row0 = t >> 4;
            const int dq = (t & 15) * 4;
#pragma unroll
            for (int it = 0; it < 4; ++it) {
                int row = row0 + it * 16;
                *reinterpret_cast<float4*>(&KVs[row][dq]) =
                    *reinterpret_cast<const float4*>(Vh + (size_t)(k0 + row) * HDIM + dq);
            }
        }
        __syncthreads();

        // PV: acc[i][j] += P[r0+i][c] * V[c][x0+j]
#pragma unroll 4
        for (int c = 0; c < 64; ++c) {
            int ph = ty ^ ((c >> 2) & 15);
            float4 pa = *reinterpret_cast<const float4*>(&Ps[c][ph * 8]);
            float4 pb = *reinterpret_cast<const float4*>(&Ps[c][ph * 8 + 4]);
            float4 vv = *reinterpret_cast<const float4*>(&KVs[c][x0]);
            acc[0][0] += pa.x * vv.x; acc[0][1] += pa.x * vv.y; acc[0][2] += pa.x * vv.z; acc[0][3] += pa.x * vv.w;
            acc[1][0] += pa.y * vv.x; acc[1][1] += pa.y * vv.y; acc[1][2] += pa.y * vv.z; acc[1][3] += pa.y * vv.w;
            acc[2][0] += pa.z * vv.x; acc[2][1] += pa.z * vv.y; acc[2][2] += pa.z * vv.z; acc[2][3] += pa.z * vv.w;
            acc[3][0] += pa.w * vv.x; acc[3][1] += pa.w * vv.y; acc[3][2] += pa.w * vv.z; acc[3][3] += pa.w * vv.w;
            acc[4][0] += pb.x * vv.x; acc[4][1] += pb.x * vv.y; acc[4][2] += pb.x * vv.z; acc[4][3] += pb.x * vv.w;
            acc[5][0] += pb.y * vv.x; acc[5][1] += pb.y * vv.y; acc[5][2] += pb.y * vv.z; acc[5][3] += pb.y * vv.w;
            acc[6][0] += pb.z * vv.x; acc[6][1] += pb.z * vv.y; acc[6][2] += pb.z * vv.z; acc[6][3] += pb.z * vv.w;
            acc[7][0] += pb.w * vv.x; acc[7][1] += pb.w * vv.y; acc[7][2] += pb.w * vv.z; acc[7][3] += pb.w * vv.w;
        }
    }

    // Normalize and write ctx
    const int b = bh >> 5;
    const int h = bh & 31;
#pragma unroll
    for (int i = 0; i < 8; ++i) {
        float inv_l = 1.0f / l[i];
        int row = q0 + r0 + i;
        float4 o;
        o.x = acc[i][0] * inv_l;
        o.y = acc[i][1] * inv_l;
        o.z = acc[i][2] * inv_l;
        o.w = acc[i][3] * inv_l;
        *reinterpret_cast<float4*>(g_ctx + (size_t)(row * BATCH + b) * EMB + h * HDIM + x0) = o;
    }
}

// ---------------------------------------------------------------------------
// Launch
// ---------------------------------------------------------------------------
extern "C" void kernel_launch(void* const* d_in, const int* in_sizes, int n_in,
                              void* d_out, int out_size) {
    const float* hs    = (const float*)d_in[0];
    const float* qkv_w = (const float*)d_in[1];
    const float* qkv_b = (const float*)d_in[2];
    const float* out_w = (const float*)d_in[3];
    const float* out_b = (const float*)d_in[4];
    float* out = (float*)d_out;

    cudaFuncSetAttribute(gemm_mma_bf16, cudaFuncAttributeMaxDynamicSharedMemorySize, GEMM_SMEM);
    cudaFuncSetAttribute(attn_kernel, cudaFuncAttributeMaxDynamicSharedMemorySize, ATTN_SMEM);

    float *qkv, *ctx;
    __nv_bfloat16 *A3, *B3q, *B3o;
    cudaGetSymbolAddress((void**)&qkv, g_qkv);
    cudaGetSymbolAddress((void**)&ctx, g_ctx);
    cudaGetSymbolAddress((void**)&A3,  g_A3);
    cudaGetSymbolAddress((void**)&B3q, g_B3q);
    cudaGetSymbolAddress((void**)&B3o, g_B3o);

    // Weight conversions (transpose + hi/lo split)
    {
        dim3 blk(32, 32);
        convB_kernel<<<dim3(QKV_N / 32, EMB / 32), blk>>>(qkv_w, B3q, QKV_N);
        convB_kernel<<<dim3(EMB / 32, EMB / 32), blk>>>(out_w, B3o, EMB);
    }
    convA_kernel<<<MROWS * 512 / 256, 256>>>(hs, A3);

    // 1. QKV projection (HMMA)
    gemm_mma_bf16<<<dim3(QKV_N / 128, MROWS / 128), 256, GEMM_SMEM>>>(QKV_N, A3, B3q, qkv_b, qkv);

    // 2. RoPE + split
    rope_split_kernel<<<(S_LEN * BATCH * HEADS * HDIM) / 256, 256>>>();

    // 3. Causal attention
    attn_kernel<<<dim3(S_LEN / 128, BATCH * HEADS), 256, ATTN_SMEM>>>();

    // 4. ctx conversion + output projection (HMMA)
    convA_kernel<<<MROWS * 512 / 256, 256>>>(ctx, A3);
    gemm_mma_bf16<<<dim3(EMB / 128, MROWS / 128), 256, GEMM_SMEM>>>(EMB, A3, B3o, out_b, out);
}